// round 6
// baseline (speedup 1.0000x reference)
#include <cuda_runtime.h>

#define EPS 1e-4f
constexpr int IN_DIM = 30;
constexpr int D1 = 20;
constexpr int D2 = 15;
constexpr int WPB = 4;          // warps (matrices) per block
constexpr int SW1 = 5, SW2 = 5; // Jacobi sweeps per stage
constexpr unsigned FULL = 0xffffffffu;

// Tournament migration: NEW[l] = OLD[sigma(l)]. Position 0 fixed.
__host__ __device__ constexpr int sigma(int N, int l) {
    if (l >= N) return l;
    if (l == 0) return 0;
    if (l == N - 1) return N - 2;
    if (l & 1) return l + 2;   // odd slots move down the ring
    if (l == 2) return 1;
    return l - 2;              // even slots >= 4
}

// One Jacobi tournament round; fully inlined, called from an unrolled loop so
// the register permutations in the migration step become pure renames.
template <int N>
__device__ __forceinline__ void jacobi_round(float* a, float* vt, float& dg,
                                             int lane, int sig, int role) {
    // --- gather rotation inputs ---
    float d_oth = __shfl_xor_sync(FULL, dg, 1);
    float off = 0.0f;
    #pragma unroll
    for (int k = 0; k < N / 2; ++k)
        if ((lane >> 1) == k) off = role ? a[2 * k] : a[2 * k + 1];
    float apq = __shfl_sync(FULL, off, lane & ~1);  // canonical copy
    float d_e = role ? d_oth : dg;
    float d_o = role ? dg : d_oth;
    // --- rotation (Golub): zero A[p][q]; identical on both pair lanes ---
    float c = 1.0f, s = 0.0f, t = 0.0f;
    if (fabsf(apq) > 1e-30f) {
        float tau = (d_o - d_e) / (2.0f * apq);
        t = copysignf(1.0f, tau) / (fabsf(tau) + sqrtf(fmaf(tau, tau, 1.0f)));
        c = rsqrtf(fmaf(t, t, 1.0f));
        s = t * c;
    }
    // --- column phase: A <- A*J (partner exchange via shfl_xor) ---
    float sg = role ? s : -s;
    #pragma unroll
    for (int i = 0; i < N; ++i) {
        float o = __shfl_xor_sync(FULL, a[i], 1);
        a[i] = fmaf(c, a[i], sg * o);
    }
    // --- analytic diag update ---
    dg = role ? fmaf(t, apq, dg) : fmaf(-t, apq, dg);
    // --- row phase: A <- J^T*(A*J); V <- V*J (static reg indices) ---
    #pragma unroll
    for (int k = 0; k < N / 2; ++k) {
        float ck = __shfl_sync(FULL, c, 2 * k);
        float sk = __shfl_sync(FULL, s, 2 * k);
        float ae = a[2 * k], ao = a[2 * k + 1];
        a[2 * k]     = fmaf(ck, ae, -sk * ao);
        a[2 * k + 1] = fmaf(sk, ae,  ck * ao);
        float ve = vt[2 * k], vo = vt[2 * k + 1];
        vt[2 * k]     = fmaf(ck, ve, -sk * vo);
        vt[2 * k + 1] = fmaf(sk, ve,  ck * vo);
    }
    // --- tournament migration: rows (renamed reg perm) + cols (lane shfl) ---
    float tmp[N];
    #pragma unroll
    for (int i = 0; i < N; ++i) tmp[i] = a[sigma(N, i)];
    #pragma unroll
    for (int i = 0; i < N; ++i) a[i] = __shfl_sync(FULL, tmp[i], sig);
    #pragma unroll
    for (int i = 0; i < N; ++i) tmp[i] = vt[sigma(N, i)];
    #pragma unroll
    for (int i = 0; i < N; ++i) vt[i] = tmp[i];
    dg = __shfl_sync(FULL, dg, sig);
}

// Sweep loop rolled (caps code size); round loop FULLY UNROLLED so that the
// per-round register permutations are absorbed by renaming. sigma has order
// N-1, so a full sweep composes to the identity layout.
template <int N>
__device__ __forceinline__ void jacobi_reg(float* a, float* vt, float& dg,
                                           int lane, int sig, int sweeps) {
    const int role = lane & 1;
    #pragma unroll 1
    for (int sw = 0; sw < sweeps; ++sw) {
        #pragma unroll
        for (int r = 0; r < N - 1; ++r)
            jacobi_round<N>(a, vt, dg, lane, sig, role);
    }
}

__global__ __launch_bounds__(WPB * 32, 7)
void spdnet_kernel(const float* __restrict__ Xg,
                   const float* __restrict__ W1g,
                   const float* __restrict__ W2g,
                   float* __restrict__ out, int nb) {
    __shared__ float W1s[D1 * IN_DIM];           // 20x30
    __shared__ float W2s[D2 * D1];               // 15x20
    __shared__ __align__(16) float scr_all[WPB][960];

    int tid = threadIdx.x, warp = tid >> 5, lane = tid & 31;
    for (int i = tid; i < D1 * IN_DIM; i += WPB * 32) W1s[i] = W1g[i];
    for (int i = tid; i < D2 * D1;    i += WPB * 32) W2s[i] = W2g[i];
    __syncthreads();

    int m = blockIdx.x * WPB + warp;
    if (m >= nb) return;           // warp-uniform; only warp-level sync below
    float* scr = scr_all[warp];

    // ================= Load X (pitch 32) and symmetrize =================
    {
        const float* xg = Xg + (size_t)m * 900;
        for (int e = lane; e < 900; e += 32) {
            int i = e / 30, k = e - i * 30;
            scr[i * 32 + k] = xg[e];
        }
        for (int e = lane; e < 60; e += 32)            // zero pad cols 30,31
            scr[(e >> 1) * 32 + 30 + (e & 1)] = 0.0f;
    }
    __syncwarp();
    for (int e = lane; e < 900; e += 32) {
        int i = e / 30, k = e - i * 30;
        if (i < k) {
            float v = 0.5f * (scr[i * 32 + k] + scr[k * 32 + i]);
            scr[i * 32 + k] = v; scr[k * 32 + i] = v;
        }
    }
    __syncwarp();

    // ================= bimap1: A = W1 * Xs * W1^T + EPS*I ===============
    float a[D1], vt[D1], dg = 1.0f;
    #pragma unroll
    for (int i = 0; i < D1; ++i) { a[i] = 0.0f; vt[i] = 0.0f; }
    if (lane < D1) {
        float wreg[32];
        #pragma unroll
        for (int k = 0; k < IN_DIM; ++k) wreg[k] = W1s[lane * IN_DIM + k];
        wreg[30] = 0.0f; wreg[31] = 0.0f;
        float t[IN_DIM];
        for (int i = 0; i < IN_DIM; ++i) {        // t = Xs * w1_lane
            const float4* x4 = reinterpret_cast<const float4*>(&scr[i * 32]);
            float acc = 0.0f;
            #pragma unroll
            for (int q = 0; q < 8; ++q) {
                float4 x = x4[q];
                acc = fmaf(x.x, wreg[4 * q + 0], acc);
                acc = fmaf(x.y, wreg[4 * q + 1], acc);
                acc = fmaf(x.z, wreg[4 * q + 2], acc);
                acc = fmaf(x.w, wreg[4 * q + 3], acc);
            }
            t[i] = acc;
        }
        #pragma unroll
        for (int r = 0; r < D1; ++r) {            // a = W1 * t (column `lane`)
            float acc = 0.0f;
            #pragma unroll
            for (int i = 0; i < IN_DIM; ++i)
                acc = fmaf(W1s[r * IN_DIM + i], t[i], acc);
            a[r] = acc;
            if (r == lane) { a[r] += EPS; dg = a[r]; }
        }
        #pragma unroll
        for (int k = 0; k < D1; ++k) vt[k] = (k == lane) ? 1.0f : 0.0f;
    }

    // ================= eigensolve 20x20 =================================
    jacobi_reg<D1>(a, vt, dg, lane, sigma(D1, lane), SW1);

    // ====== fused reeig + bimap2: C = Z Z^T,  Z = W2 * (V * sqrt(g)) ====
    float g = sqrtf(fmaxf(dg, EPS));
    #pragma unroll
    for (int k = 0; k < D1; ++k) {
        float rk = __shfl_sync(FULL, g, k);
        vt[k] *= rk;
    }
    if (lane < D1) {
        #pragma unroll
        for (int k = 0; k < D1; ++k) scr[lane * 24 + k] = vt[k]; // Vs (pitch 24)
    }
    __syncwarp();
    float z[D1];
    #pragma unroll
    for (int k = 0; k < D1; ++k) z[k] = 0.0f;
    if (lane < D2) {
        float w2r[D1];
        #pragma unroll
        for (int r = 0; r < D1; ++r) w2r[r] = W2s[lane * D1 + r];
        for (int r = 0; r < D1; ++r) {
            const float4* v4 = reinterpret_cast<const float4*>(&scr[r * 24]);
            float w = w2r[r];
            #pragma unroll
            for (int q = 0; q < 5; ++q) {
                float4 x = v4[q];
                z[4 * q + 0] = fmaf(w, x.x, z[4 * q + 0]);
                z[4 * q + 1] = fmaf(w, x.y, z[4 * q + 1]);
                z[4 * q + 2] = fmaf(w, x.z, z[4 * q + 2]);
                z[4 * q + 3] = fmaf(w, x.w, z[4 * q + 3]);
            }
        }
    }
    __syncwarp();
    if (lane < D2) {
        #pragma unroll
        for (int k = 0; k < D1; ++k) scr[480 + lane * 24 + k] = z[k]; // Zs
    }
    __syncwarp();

    float a2[16], vt2[16], dg2 = 1.0f;
    #pragma unroll
    for (int i = 0; i < 16; ++i) { a2[i] = 0.0f; vt2[i] = 0.0f; }
    if (lane < 16) {
        #pragma unroll
        for (int b = 0; b < D2; ++b) {            // A2[b][lane] = Zrow_b . z
            const float4* zb = reinterpret_cast<const float4*>(&scr[480 + b * 24]);
            float acc = 0.0f;
            #pragma unroll
            for (int q = 0; q < 5; ++q) {
                float4 x = zb[q];
                acc = fmaf(x.x, z[4 * q + 0], acc);
                acc = fmaf(x.y, z[4 * q + 1], acc);
                acc = fmaf(x.z, z[4 * q + 2], acc);
                acc = fmaf(x.w, z[4 * q + 3], acc);
            }
            a2[b] = acc;
        }
        a2[15] = 0.0f;                            // padded dim decoupled
        #pragma unroll
        for (int b = 0; b < 16; ++b)
            if (b == lane) { a2[b] += EPS; dg2 = a2[b]; }
        #pragma unroll
        for (int k = 0; k < 16; ++k) vt2[k] = (k == lane) ? 1.0f : 0.0f;
    }

    // ================= eigensolve 16x16 (15 + 1 padded) =================
    jacobi_reg<16>(a2, vt2, dg2, lane, sigma(16, lane), SW2);

    // ============== logeig recompose, upper-triangle output =============
    float lw = logf(fmaxf(dg2, EPS));
    #pragma unroll
    for (int k = 0; k < 16; ++k) {
        float lwk = __shfl_sync(FULL, lw, k);
        float raw = vt2[k];
        if (lane < D2) {
            scr[lane * 16 + k]       = raw;        // raw rows of V2
            scr[256 + lane * 16 + k] = raw * lwk;  // scaled rows
        }
    }
    __syncwarp();
    for (int tt = lane; tt < 120; tt += 32) {
        int i = 0, rem = tt;
        while (rem >= D2 - i) { rem -= D2 - i; ++i; }
        int j = i + rem;
        const float4* ri = reinterpret_cast<const float4*>(&scr[256 + i * 16]);
        const float4* rj = reinterpret_cast<const float4*>(&scr[j * 16]);
        float acc = 0.0f;
        #pragma unroll
        for (int q = 0; q < 4; ++q) {
            float4 x = ri[q], y = rj[q];
            acc = fmaf(x.x, y.x, fmaf(x.y, y.y, fmaf(x.z, y.z, fmaf(x.w, y.w, acc))));
        }
        out[(size_t)m * 120 + tt] = acc;
    }
}

extern "C" void kernel_launch(void* const* d_in, const int* in_sizes, int n_in,
                              void* d_out, int out_size) {
    const float* X  = (const float*)d_in[0];
    const float* W1 = (const float*)d_in[1];
    const float* W2 = (const float*)d_in[2];
    float* out = (float*)d_out;
    int nb = in_sizes[0] / (IN_DIM * IN_DIM);
    int blocks = (nb + WPB - 1) / WPB;
    spdnet_kernel<<<blocks, WPB * 32>>>(X, W1, W2, out, nb);
}

// round 7
// speedup vs baseline: 1.3735x; 1.3735x over previous
#include <cuda_runtime.h>

#define EPS 1e-4f
constexpr int IN_DIM = 30;
constexpr int D1 = 20;
constexpr int D2 = 15;
constexpr int WPB = 4;          // warps per block
constexpr int SW1 = 5, SW2 = 5; // Jacobi sweeps per stage
constexpr int MAXB = 65536;
constexpr unsigned FULL = 0xffffffffu;

// Inter-kernel scratch: A2 columns, [m][col(16)][row(16)]
__device__ float g_A2[(size_t)MAXB * 256];

// Tournament migration: NEW[l] = OLD[sigma(l)]. Position 0 fixed.
__host__ __device__ constexpr int sigma(int N, int l) {
    if (l >= N) return l;
    if (l == 0) return 0;
    if (l == N - 1) return N - 2;
    if (l & 1) return l + 2;   // odd slots move down the ring
    if (l == 2) return 1;
    return l - 2;              // even slots >= 4
}

// Register/shuffle parallel Jacobi over width-W lane groups.
// llane = group-relative lane; pairs are fixed group-lanes (2k,2k+1).
template <int N, int W>
__device__ __forceinline__ void jacobi_reg(float* a, float* vt, float& dg,
                                           int llane, int sig, int sweeps) {
    const int role = llane & 1;
    #pragma unroll 1
    for (int sw = 0; sw < sweeps; ++sw) {
        #pragma unroll 1
        for (int r = 0; r < N - 1; ++r) {
            // --- gather rotation inputs ---
            float d_oth = __shfl_xor_sync(FULL, dg, 1);
            float off = 0.0f;
            #pragma unroll
            for (int k = 0; k < N / 2; ++k)
                if ((llane >> 1) == k) off = role ? a[2 * k] : a[2 * k + 1];
            float apq = __shfl_sync(FULL, off, llane & ~1, W);  // canonical
            float d_e = role ? d_oth : dg;
            float d_o = role ? dg : d_oth;
            // --- rotation; bit-identical on both pair lanes ---
            float c = 1.0f, s = 0.0f, t = 0.0f;
            if (fabsf(apq) > 1e-30f) {
                float tau = (d_o - d_e) / (2.0f * apq);
                t = copysignf(1.0f, tau) / (fabsf(tau) + sqrtf(fmaf(tau, tau, 1.0f)));
                c = rsqrtf(fmaf(t, t, 1.0f));
                s = t * c;
            }
            // --- column phase: A <- A*J ---
            float sg = role ? s : -s;
            #pragma unroll
            for (int i = 0; i < N; ++i) {
                float o = __shfl_xor_sync(FULL, a[i], 1);
                a[i] = fmaf(c, a[i], sg * o);
            }
            // --- analytic diag update ---
            dg = role ? fmaf(t, apq, dg) : fmaf(-t, apq, dg);
            // --- row phase: A <- J^T*(A*J); V <- V*J ---
            #pragma unroll
            for (int k = 0; k < N / 2; ++k) {
                float ck = __shfl_sync(FULL, c, 2 * k, W);
                float sk = __shfl_sync(FULL, s, 2 * k, W);
                float ae = a[2 * k], ao = a[2 * k + 1];
                a[2 * k]     = fmaf(ck, ae, -sk * ao);
                a[2 * k + 1] = fmaf(sk, ae,  ck * ao);
                float ve = vt[2 * k], vo = vt[2 * k + 1];
                vt[2 * k]     = fmaf(ck, ve, -sk * vo);
                vt[2 * k + 1] = fmaf(sk, ve,  ck * vo);
            }
            // --- tournament migration ---
            float tmp[N];
            #pragma unroll
            for (int i = 0; i < N; ++i) tmp[i] = a[sigma(N, i)];
            #pragma unroll
            for (int i = 0; i < N; ++i) a[i] = __shfl_sync(FULL, tmp[i], sig, W);
            #pragma unroll
            for (int i = 0; i < N; ++i) tmp[i] = vt[sigma(N, i)];
            #pragma unroll
            for (int i = 0; i < N; ++i) vt[i] = tmp[i];
            dg = __shfl_sync(FULL, dg, sig, W);
        }
    }
}

// ================= Kernel 1: stage 1 (X -> A2 in scratch) ==================
__global__ __launch_bounds__(WPB * 32, 7)
void spdnet_stage1(const float* __restrict__ Xg,
                   const float* __restrict__ W1g,
                   const float* __restrict__ W2g, int nb) {
    __shared__ float W1s[D1 * IN_DIM];
    __shared__ float W2s[D2 * D1];
    __shared__ __align__(16) float scr_all[WPB][960];

    int tid = threadIdx.x, warp = tid >> 5, lane = tid & 31;
    for (int i = tid; i < D1 * IN_DIM; i += WPB * 32) W1s[i] = W1g[i];
    for (int i = tid; i < D2 * D1;    i += WPB * 32) W2s[i] = W2g[i];
    __syncthreads();

    int m = blockIdx.x * WPB + warp;
    if (m >= nb) return;
    float* scr = scr_all[warp];

    // ---- load X (pitch 32), pad, symmetrize ----
    {
        const float* xg = Xg + (size_t)m * 900;
        for (int e = lane; e < 900; e += 32) {
            int i = e / 30, k = e - i * 30;
            scr[i * 32 + k] = xg[e];
        }
        for (int e = lane; e < 60; e += 32)
            scr[(e >> 1) * 32 + 30 + (e & 1)] = 0.0f;
    }
    __syncwarp();
    for (int e = lane; e < 900; e += 32) {
        int i = e / 30, k = e - i * 30;
        if (i < k) {
            float v = 0.5f * (scr[i * 32 + k] + scr[k * 32 + i]);
            scr[i * 32 + k] = v; scr[k * 32 + i] = v;
        }
    }
    __syncwarp();

    // ---- bimap1: A = W1 * Xs * W1^T + EPS*I (column per lane) ----
    float a[D1], vt[D1], dg = 1.0f;
    #pragma unroll
    for (int i = 0; i < D1; ++i) { a[i] = 0.0f; vt[i] = 0.0f; }
    if (lane < D1) {
        float wreg[32];
        #pragma unroll
        for (int k = 0; k < IN_DIM; ++k) wreg[k] = W1s[lane * IN_DIM + k];
        wreg[30] = 0.0f; wreg[31] = 0.0f;
        float t[IN_DIM];
        for (int i = 0; i < IN_DIM; ++i) {
            const float4* x4 = reinterpret_cast<const float4*>(&scr[i * 32]);
            float acc = 0.0f;
            #pragma unroll
            for (int q = 0; q < 8; ++q) {
                float4 x = x4[q];
                acc = fmaf(x.x, wreg[4 * q + 0], acc);
                acc = fmaf(x.y, wreg[4 * q + 1], acc);
                acc = fmaf(x.z, wreg[4 * q + 2], acc);
                acc = fmaf(x.w, wreg[4 * q + 3], acc);
            }
            t[i] = acc;
        }
        #pragma unroll
        for (int r = 0; r < D1; ++r) {
            float acc = 0.0f;
            #pragma unroll
            for (int i = 0; i < IN_DIM; ++i)
                acc = fmaf(W1s[r * IN_DIM + i], t[i], acc);
            a[r] = acc;
            if (r == lane) { a[r] += EPS; dg = a[r]; }
        }
        #pragma unroll
        for (int k = 0; k < D1; ++k) vt[k] = (k == lane) ? 1.0f : 0.0f;
    }

    // ---- eigensolve 20x20 ----
    jacobi_reg<D1, 32>(a, vt, dg, lane, sigma(D1, lane), SW1);

    // ---- fused reeig + bimap2: A2 = Z Z^T + EPS*I, Z = W2*(V*sqrt(g)) ----
    float g = sqrtf(fmaxf(dg, EPS));
    #pragma unroll
    for (int k = 0; k < D1; ++k) {
        float rk = __shfl_sync(FULL, g, k);
        vt[k] *= rk;
    }
    if (lane < D1) {
        #pragma unroll
        for (int k = 0; k < D1; ++k) scr[lane * 24 + k] = vt[k];  // Vs pitch 24
    }
    __syncwarp();
    float z[D1];
    #pragma unroll
    for (int k = 0; k < D1; ++k) z[k] = 0.0f;
    if (lane < D2) {
        float w2r[D1];
        #pragma unroll
        for (int r = 0; r < D1; ++r) w2r[r] = W2s[lane * D1 + r];
        for (int r = 0; r < D1; ++r) {
            const float4* v4 = reinterpret_cast<const float4*>(&scr[r * 24]);
            float w = w2r[r];
            #pragma unroll
            for (int q = 0; q < 5; ++q) {
                float4 x = v4[q];
                z[4 * q + 0] = fmaf(w, x.x, z[4 * q + 0]);
                z[4 * q + 1] = fmaf(w, x.y, z[4 * q + 1]);
                z[4 * q + 2] = fmaf(w, x.z, z[4 * q + 2]);
                z[4 * q + 3] = fmaf(w, x.w, z[4 * q + 3]);
            }
        }
    }
    __syncwarp();
    if (lane < D2) {
        #pragma unroll
        for (int k = 0; k < D1; ++k) scr[480 + lane * 24 + k] = z[k];  // Zs
    }
    __syncwarp();

    if (lane < 16) {
        float a2[16];
        #pragma unroll
        for (int b = 0; b < D2; ++b) {
            const float4* zb = reinterpret_cast<const float4*>(&scr[480 + b * 24]);
            float acc = 0.0f;
            #pragma unroll
            for (int q = 0; q < 5; ++q) {
                float4 x = zb[q];
                acc = fmaf(x.x, z[4 * q + 0], acc);
                acc = fmaf(x.y, z[4 * q + 1], acc);
                acc = fmaf(x.z, z[4 * q + 2], acc);
                acc = fmaf(x.w, z[4 * q + 3], acc);
            }
            a2[b] = acc;
        }
        a2[15] = 0.0f;
        a2[lane] += EPS;   // lane<16 column diag (lane 15 pad gets EPS too: isolated)
        float4* dst = reinterpret_cast<float4*>(&g_A2[(size_t)m * 256 + lane * 16]);
        const float4* src = reinterpret_cast<const float4*>(a2);
        #pragma unroll
        for (int q = 0; q < 4; ++q) dst[q] = src[q];
    }
}

// ====== Kernel 2: dual 16x16 eigensolve + logeig + triangle output =========
__global__ __launch_bounds__(WPB * 32, 8)
void spdnet_stage2(float* __restrict__ out, int nb) {
    __shared__ __align__(16) float scr_all[WPB][1024];
    int tid = threadIdx.x, warp = tid >> 5, lane = tid & 31;
    int npairs = (nb + 1) >> 1;
    int wm = blockIdx.x * WPB + warp;
    if (wm >= npairs) return;
    float* scr = scr_all[warp];

    int g = lane >> 4, llane = lane & 15;
    int m = 2 * wm + g;
    int ml = m < nb ? m : nb - 1;

    float a2[16], vt2[16];
    {
        const float4* src = reinterpret_cast<const float4*>(&g_A2[(size_t)ml * 256 + llane * 16]);
        float4* dst = reinterpret_cast<float4*>(a2);
        #pragma unroll
        for (int q = 0; q < 4; ++q) dst[q] = src[q];
    }
    float dg2 = a2[llane];
    #pragma unroll
    for (int k = 0; k < 16; ++k) vt2[k] = (k == llane) ? 1.0f : 0.0f;

    jacobi_reg<16, 16>(a2, vt2, dg2, llane, sigma(16, llane), SW2);

    // logeig recompose into smem
    float lw = logf(fmaxf(dg2, EPS));
    #pragma unroll
    for (int k = 0; k < 16; ++k) {
        float lwk = __shfl_sync(FULL, lw, k, 16);
        float raw = vt2[k];
        if (llane < D2) {
            scr[g * 512 + llane * 16 + k]       = raw;        // raw rows of V2
            scr[g * 512 + 256 + llane * 16 + k] = raw * lwk;  // scaled rows
        }
    }
    __syncwarp();

    // each 16-lane group writes its matrix's 120 outputs
    if (m < nb) {
        const float* base = &scr[g * 512];
        for (int tt = llane; tt < 120; tt += 16) {
            int i = 0, rem = tt;
            while (rem >= D2 - i) { rem -= D2 - i; ++i; }
            int j = i + rem;
            const float4* ri = reinterpret_cast<const float4*>(&base[256 + i * 16]);
            const float4* rj = reinterpret_cast<const float4*>(&base[j * 16]);
            float acc = 0.0f;
            #pragma unroll
            for (int q = 0; q < 4; ++q) {
                float4 x = ri[q], y = rj[q];
                acc = fmaf(x.x, y.x, fmaf(x.y, y.y, fmaf(x.z, y.z, fmaf(x.w, y.w, acc))));
            }
            out[(size_t)m * 120 + tt] = acc;
        }
    }
}

extern "C" void kernel_launch(void* const* d_in, const int* in_sizes, int n_in,
                              void* d_out, int out_size) {
    const float* X  = (const float*)d_in[0];
    const float* W1 = (const float*)d_in[1];
    const float* W2 = (const float*)d_in[2];
    float* out = (float*)d_out;
    int nb = in_sizes[0] / (IN_DIM * IN_DIM);
    if (nb > MAXB) nb = MAXB;
    int blocks1 = (nb + WPB - 1) / WPB;
    spdnet_stage1<<<blocks1, WPB * 32>>>(X, W1, W2, nb);
    int npairs = (nb + 1) / 2;
    int blocks2 = (npairs + WPB - 1) / WPB;
    spdnet_stage2<<<blocks2, WPB * 32>>>(out, nb);
}

// round 8
// speedup vs baseline: 1.5927x; 1.1595x over previous
#include <cuda_runtime.h>

#define EPS 1e-4f
constexpr int IN_DIM = 30;
constexpr int D1 = 20;
constexpr int D2 = 15;
constexpr int WPB = 4;          // warps (matrices) per block
constexpr int SW1 = 5, SW2 = 5; // Jacobi sweeps per stage
constexpr unsigned FULL = 0xffffffffu;

// Tournament migration: NEW[l] = OLD[sigma(l)]. Position 0 fixed.
__host__ __device__ constexpr int sigma(int N, int l) {
    if (l >= N) return l;
    if (l == 0) return 0;
    if (l == N - 1) return N - 2;
    if (l & 1) return l + 2;   // odd slots move down the ring
    if (l == 2) return 1;
    return l - 2;              // even slots >= 4
}

// Register/shuffle parallel Jacobi. Lane = column position of A; pairs are
// fixed lanes (2k,2k+1); vt = row `lane` of V (columns = positions).
template <int N>
__device__ __forceinline__ void jacobi_reg(float* a, float* vt, float& dg,
                                           int lane, int sig, int sweeps) {
    const int role = lane & 1;           // 0 = p-role (even pos), 1 = q-role
    #pragma unroll 1
    for (int sw = 0; sw < sweeps; ++sw) {
        #pragma unroll 1
        for (int r = 0; r < N - 1; ++r) {
            // --- gather rotation inputs ---
            float d_oth = __shfl_xor_sync(FULL, dg, 1);
            float off = 0.0f;
            #pragma unroll
            for (int k = 0; k < N / 2; ++k)
                if ((lane >> 1) == k) off = role ? a[2 * k] : a[2 * k + 1];
            float apq = __shfl_sync(FULL, off, lane & ~1);  // canonical copy
            float d_e = role ? d_oth : dg;
            float d_o = role ? dg : d_oth;
            // --- rotation (Golub): zero A[p][q]; identical on both pair lanes ---
            float c = 1.0f, s = 0.0f, t = 0.0f;
            if (fabsf(apq) > 1e-30f) {
                float tau = (d_o - d_e) / (2.0f * apq);
                t = copysignf(1.0f, tau) / (fabsf(tau) + sqrtf(fmaf(tau, tau, 1.0f)));
                c = rsqrtf(fmaf(t, t, 1.0f));
                s = t * c;
            }
            // --- column phase: A <- A*J (partner exchange via shfl_xor) ---
            float sg = role ? s : -s;
            #pragma unroll
            for (int i = 0; i < N; ++i) {
                float o = __shfl_xor_sync(FULL, a[i], 1);
                a[i] = fmaf(c, a[i], sg * o);
            }
            // --- analytic diag update ---
            dg = role ? fmaf(t, apq, dg) : fmaf(-t, apq, dg);
            // --- row phase: A <- J^T*(A*J); V <- V*J (static reg indices) ---
            #pragma unroll
            for (int k = 0; k < N / 2; ++k) {
                float ck = __shfl_sync(FULL, c, 2 * k);
                float sk = __shfl_sync(FULL, s, 2 * k);
                float ae = a[2 * k], ao = a[2 * k + 1];
                a[2 * k]     = fmaf(ck, ae, -sk * ao);
                a[2 * k + 1] = fmaf(sk, ae,  ck * ao);
                float ve = vt[2 * k], vo = vt[2 * k + 1];
                vt[2 * k]     = fmaf(ck, ve, -sk * vo);
                vt[2 * k + 1] = fmaf(sk, ve,  ck * vo);
            }
            // --- tournament migration: rows (reg perm) + cols (lane shfl) ---
            float tmp[N];
            #pragma unroll
            for (int i = 0; i < N; ++i) tmp[i] = a[sigma(N, i)];
            #pragma unroll
            for (int i = 0; i < N; ++i) a[i] = __shfl_sync(FULL, tmp[i], sig);
            #pragma unroll
            for (int i = 0; i < N; ++i) tmp[i] = vt[sigma(N, i)];
            #pragma unroll
            for (int i = 0; i < N; ++i) vt[i] = tmp[i];
            dg = __shfl_sync(FULL, dg, sig);
        }
    }
}

__global__ __launch_bounds__(WPB * 32, 8)
void spdnet_kernel(const float* __restrict__ Xg,
                   const float* __restrict__ W1g,
                   const float* __restrict__ W2g,
                   float* __restrict__ out, int nb) {
    __shared__ float W1s[D1 * IN_DIM];           // 20x30
    __shared__ float W2s[D2 * D1];               // 15x20
    __shared__ __align__(16) float scr_all[WPB][960];

    int tid = threadIdx.x, warp = tid >> 5, lane = tid & 31;
    for (int i = tid; i < D1 * IN_DIM; i += WPB * 32) W1s[i] = W1g[i];
    for (int i = tid; i < D2 * D1;    i += WPB * 32) W2s[i] = W2g[i];
    __syncthreads();

    int m = blockIdx.x * WPB + warp;
    if (m >= nb) return;           // warp-uniform; only warp-level sync below
    float* scr = scr_all[warp];

    // ================= Load X (pitch 32) and symmetrize =================
    {
        const float* xg = Xg + (size_t)m * 900;
        for (int e = lane; e < 900; e += 32) {
            int i = e / 30, k = e - i * 30;
            scr[i * 32 + k] = xg[e];
        }
        for (int e = lane; e < 60; e += 32)            // zero pad cols 30,31
            scr[(e >> 1) * 32 + 30 + (e & 1)] = 0.0f;
    }
    __syncwarp();
    for (int e = lane; e < 900; e += 32) {
        int i = e / 30, k = e - i * 30;
        if (i < k) {
            float v = 0.5f * (scr[i * 32 + k] + scr[k * 32 + i]);
            scr[i * 32 + k] = v; scr[k * 32 + i] = v;
        }
    }
    __syncwarp();

    // ================= bimap1: A = W1 * Xs * W1^T + EPS*I ===============
    float a[D1], vt[D1], dg = 1.0f;
    #pragma unroll
    for (int i = 0; i < D1; ++i) { a[i] = 0.0f; vt[i] = 0.0f; }
    if (lane < D1) {
        float wreg[32];
        #pragma unroll
        for (int k = 0; k < IN_DIM; ++k) wreg[k] = W1s[lane * IN_DIM + k];
        wreg[30] = 0.0f; wreg[31] = 0.0f;
        float t[IN_DIM];
        for (int i = 0; i < IN_DIM; ++i) {        // t = Xs * w1_lane
            const float4* x4 = reinterpret_cast<const float4*>(&scr[i * 32]);
            float acc = 0.0f;
            #pragma unroll
            for (int q = 0; q < 8; ++q) {
                float4 x = x4[q];
                acc = fmaf(x.x, wreg[4 * q + 0], acc);
                acc = fmaf(x.y, wreg[4 * q + 1], acc);
                acc = fmaf(x.z, wreg[4 * q + 2], acc);
                acc = fmaf(x.w, wreg[4 * q + 3], acc);
            }
            t[i] = acc;
        }
        #pragma unroll
        for (int r = 0; r < D1; ++r) {            // a = W1 * t (column `lane`)
            float acc = 0.0f;
            #pragma unroll
            for (int i = 0; i < IN_DIM; ++i)
                acc = fmaf(W1s[r * IN_DIM + i], t[i], acc);
            a[r] = acc;
            if (r == lane) { a[r] += EPS; dg = a[r]; }
        }
        #pragma unroll
        for (int k = 0; k < D1; ++k) vt[k] = (k == lane) ? 1.0f : 0.0f;
    }

    // ================= eigensolve 20x20 =================================
    jacobi_reg<D1>(a, vt, dg, lane, sigma(D1, lane), SW1);

    // ====== fused reeig + bimap2: C = Z Z^T,  Z = W2 * (V * sqrt(g)) ====
    float g = sqrtf(fmaxf(dg, EPS));
    #pragma unroll
    for (int k = 0; k < D1; ++k) {
        float rk = __shfl_sync(FULL, g, k);
        vt[k] *= rk;
    }
    if (lane < D1) {
        #pragma unroll
        for (int k = 0; k < D1; ++k) scr[lane * 24 + k] = vt[k]; // Vs (pitch 24)
    }
    __syncwarp();
    float z[D1];
    #pragma unroll
    for (int k = 0; k < D1; ++k) z[k] = 0.0f;
    if (lane < D2) {
        float w2r[D1];
        #pragma unroll
        for (int r = 0; r < D1; ++r) w2r[r] = W2s[lane * D1 + r];
        for (int r = 0; r < D1; ++r) {
            const float4* v4 = reinterpret_cast<const float4*>(&scr[r * 24]);
            float w = w2r[r];
            #pragma unroll
            for (int q = 0; q < 5; ++q) {
                float4 x = v4[q];
                z[4 * q + 0] = fmaf(w, x.x, z[4 * q + 0]);
                z[4 * q + 1] = fmaf(w, x.y, z[4 * q + 1]);
                z[4 * q + 2] = fmaf(w, x.z, z[4 * q + 2]);
                z[4 * q + 3] = fmaf(w, x.w, z[4 * q + 3]);
            }
        }
    }
    __syncwarp();
    if (lane < D2) {
        #pragma unroll
        for (int k = 0; k < D1; ++k) scr[480 + lane * 24 + k] = z[k]; // Zs
    }
    __syncwarp();

    float a2[16], vt2[16], dg2 = 1.0f;
    #pragma unroll
    for (int i = 0; i < 16; ++i) { a2[i] = 0.0f; vt2[i] = 0.0f; }
    if (lane < 16) {
        #pragma unroll
        for (int b = 0; b < D2; ++b) {            // A2[b][lane] = Zrow_b . z
            const float4* zb = reinterpret_cast<const float4*>(&scr[480 + b * 24]);
            float acc = 0.0f;
            #pragma unroll
            for (int q = 0; q < 5; ++q) {
                float4 x = zb[q];
                acc = fmaf(x.x, z[4 * q + 0], acc);
                acc = fmaf(x.y, z[4 * q + 1], acc);
                acc = fmaf(x.z, z[4 * q + 2], acc);
                acc = fmaf(x.w, z[4 * q + 3], acc);
            }
            a2[b] = acc;
        }
        a2[15] = 0.0f;                            // padded dim decoupled
        #pragma unroll
        for (int b = 0; b < 16; ++b)
            if (b == lane) { a2[b] += EPS; dg2 = a2[b]; }
        #pragma unroll
        for (int k = 0; k < 16; ++k) vt2[k] = (k == lane) ? 1.0f : 0.0f;
    }

    // ================= eigensolve 16x16 (15 + 1 padded) =================
    jacobi_reg<16>(a2, vt2, dg2, lane, sigma(16, lane), SW2);

    // ============== logeig recompose, upper-triangle output =============
    float lw = logf(fmaxf(dg2, EPS));
    #pragma unroll
    for (int k = 0; k < 16; ++k) {
        float lwk = __shfl_sync(FULL, lw, k);
        float raw = vt2[k];
        if (lane < D2) {
            scr[lane * 16 + k]       = raw;        // raw rows of V2
            scr[256 + lane * 16 + k] = raw * lwk;  // scaled rows
        }
    }
    __syncwarp();
    for (int tt = lane; tt < 120; tt += 32) {
        int i = 0, rem = tt;
        while (rem >= D2 - i) { rem -= D2 - i; ++i; }
        int j = i + rem;
        const float4* ri = reinterpret_cast<const float4*>(&scr[256 + i * 16]);
        const float4* rj = reinterpret_cast<const float4*>(&scr[j * 16]);
        float acc = 0.0f;
        #pragma unroll
        for (int q = 0; q < 4; ++q) {
            float4 x = ri[q], y = rj[q];
            acc = fmaf(x.x, y.x, fmaf(x.y, y.y, fmaf(x.z, y.z, fmaf(x.w, y.w, acc))));
        }
        out[(size_t)m * 120 + tt] = acc;
    }
}

extern "C" void kernel_launch(void* const* d_in, const int* in_sizes, int n_in,
                              void* d_out, int out_size) {
    const float* X  = (const float*)d_in[0];
    const float* W1 = (const float*)d_in[1];
    const float* W2 = (const float*)d_in[2];
    float* out = (float*)d_out;
    int nb = in_sizes[0] / (IN_DIM * IN_DIM);
    int blocks = (nb + WPB - 1) / WPB;
    spdnet_kernel<<<blocks, WPB * 32>>>(X, W1, W2, out, nb);
}

// round 10
// speedup vs baseline: 1.8087x; 1.1356x over previous
#include <cuda_runtime.h>

#define EPS 1e-4f
constexpr int IN_DIM = 30;
constexpr int D1 = 20;
constexpr int D2 = 15;
constexpr int WPB = 4;          // warps (matrices) per block
constexpr int SW1 = 5, SW2 = 5; // Jacobi sweeps per stage
constexpr unsigned FULL = 0xffffffffu;

// Tournament migration: NEW[l] = OLD[sigma(l)]. Position 0 fixed.
__host__ __device__ constexpr int sigma(int N, int l) {
    if (l >= N) return l;
    if (l == 0) return 0;
    if (l == N - 1) return N - 2;
    if (l & 1) return l + 2;   // odd slots move down the ring
    if (l == 2) return 1;
    return l - 2;              // even slots >= 4
}

// Register/shuffle parallel Jacobi with a shared round-buffer for rotation
// coefficients. rb layout (floats): cs[2][N] (float2 pairs, double-buffered),
// diag[2][N/2] at rb + 2N. rb must be 16B aligned; needs 3N floats.
template <int N>
__device__ __forceinline__ void jacobi_smem(float* a, float* vt, float& dg,
                                            int lane, int sig, int sweeps,
                                            float* rb) {
    const int role = lane & 1;
    const int myk = lane >> 1;
    const int kk = (myk < N / 2) ? myk : 0;     // proper clamp (N/2 may be non-pow2)
    int buf = 0;
    #pragma unroll 1
    for (int sw = 0; sw < sweeps; ++sw) {
        #pragma unroll 1
        for (int r = 0; r < N - 1; ++r) {
            float d_oth = __shfl_xor_sync(FULL, dg, 1);
            // --- even pair-lane computes rotation, publishes via shared ---
            if (!role && lane < N) {
                float off = 0.0f;
                #pragma unroll
                for (int k = 0; k < N / 2; ++k)
                    if (myk == k) off = a[2 * k + 1];   // off-diag A[q][p]
                float c = 1.0f, s = 0.0f, t = 0.0f;
                if (fabsf(off) > 1e-30f) {
                    float tau = (d_oth - dg) / (2.0f * off);
                    t = copysignf(1.0f, tau) /
                        (fabsf(tau) + sqrtf(fmaf(tau, tau, 1.0f)));
                    c = rsqrtf(fmaf(t, t, 1.0f));
                    s = t * c;
                }
                reinterpret_cast<float2*>(rb + buf * N)[myk] = make_float2(c, s);
                rb[2 * N + buf * (N / 2) + myk] = fmaf(t, off, d_oth); // odd diag'
                dg = fmaf(-t, off, dg);                                // even diag'
            }
            __syncwarp();
            // --- own-pair coefficients (LDS.64; broadcast within pair) ---
            float2 mycs = reinterpret_cast<const float2*>(rb + buf * N)[kk];
            float c = mycs.x, s = mycs.y;
            if (role) dg = rb[2 * N + buf * (N / 2) + kk];
            // --- column phase: A <- A*J (partner exchange via shfl_xor) ---
            float sg = role ? s : -s;
            #pragma unroll
            for (int i = 0; i < N; ++i) {
                float o = __shfl_xor_sync(FULL, a[i], 1);
                a[i] = fmaf(c, a[i], sg * o);
            }
            // --- row phase: A <- J^T*(A*J); V <- V*J; cs via LDS.128 bcast ---
            const float4* csv = reinterpret_cast<const float4*>(rb + buf * N);
            #pragma unroll
            for (int k4 = 0; k4 < N / 4; ++k4) {
                float4 q = csv[k4];
                {   // pair 2*k4: rows 4*k4, 4*k4+1
                    float ck = q.x, sk = q.y;
                    float ae = a[4 * k4], ao = a[4 * k4 + 1];
                    a[4 * k4]     = fmaf(ck, ae, -sk * ao);
                    a[4 * k4 + 1] = fmaf(sk, ae,  ck * ao);
                    float ve = vt[4 * k4], vo = vt[4 * k4 + 1];
                    vt[4 * k4]     = fmaf(ck, ve, -sk * vo);
                    vt[4 * k4 + 1] = fmaf(sk, ve,  ck * vo);
                }
                {   // pair 2*k4+1: rows 4*k4+2, 4*k4+3
                    float ck = q.z, sk = q.w;
                    float ae = a[4 * k4 + 2], ao = a[4 * k4 + 3];
                    a[4 * k4 + 2] = fmaf(ck, ae, -sk * ao);
                    a[4 * k4 + 3] = fmaf(sk, ae,  ck * ao);
                    float ve = vt[4 * k4 + 2], vo = vt[4 * k4 + 3];
                    vt[4 * k4 + 2] = fmaf(ck, ve, -sk * vo);
                    vt[4 * k4 + 3] = fmaf(sk, ve,  ck * vo);
                }
            }
            // --- tournament migration: rows (reg perm) + cols (lane shfl) ---
            float tmp[N];
            #pragma unroll
            for (int i = 0; i < N; ++i) tmp[i] = a[sigma(N, i)];
            #pragma unroll
            for (int i = 0; i < N; ++i) a[i] = __shfl_sync(FULL, tmp[i], sig);
            #pragma unroll
            for (int i = 0; i < N; ++i) tmp[i] = vt[sigma(N, i)];
            #pragma unroll
            for (int i = 0; i < N; ++i) vt[i] = tmp[i];
            dg = __shfl_sync(FULL, dg, sig);
            buf ^= 1;
        }
    }
}

__global__ __launch_bounds__(WPB * 32, 7)
void spdnet_kernel(const float* __restrict__ Xg,
                   const float* __restrict__ W1g,
                   const float* __restrict__ W2g,
                   float* __restrict__ out, int nb) {
    __shared__ float W1s[D1 * IN_DIM];           // 20x30
    __shared__ float W2s[D2 * D1];               // 15x20
    __shared__ __align__(16) float scr_all[WPB][960];

    int tid = threadIdx.x, warp = tid >> 5, lane = tid & 31;
    for (int i = tid; i < D1 * IN_DIM; i += WPB * 32) W1s[i] = W1g[i];
    for (int i = tid; i < D2 * D1;    i += WPB * 32) W2s[i] = W2g[i];
    __syncthreads();

    int m = blockIdx.x * WPB + warp;
    if (m >= nb) return;           // warp-uniform; only warp-level sync below
    float* scr = scr_all[warp];
    float* rb = scr + 896;         // round buffer (16B aligned; X dead by use)

    // ================= Load X (pitch 32) and symmetrize =================
    {
        const float* xg = Xg + (size_t)m * 900;
        for (int e = lane; e < 900; e += 32) {
            int i = e / 30, k = e - i * 30;
            scr[i * 32 + k] = xg[e];
        }
        for (int e = lane; e < 60; e += 32)            // zero pad cols 30,31
            scr[(e >> 1) * 32 + 30 + (e & 1)] = 0.0f;
    }
    __syncwarp();
    for (int e = lane; e < 900; e += 32) {
        int i = e / 30, k = e - i * 30;
        if (i < k) {
            float v = 0.5f * (scr[i * 32 + k] + scr[k * 32 + i]);
            scr[i * 32 + k] = v; scr[k * 32 + i] = v;
        }
    }
    __syncwarp();

    // ================= bimap1: A = W1 * Xs * W1^T + EPS*I ===============
    float a[D1], vt[D1], dg = 1.0f;
    #pragma unroll
    for (int i = 0; i < D1; ++i) { a[i] = 0.0f; vt[i] = 0.0f; }
    if (lane < D1) {
        float wreg[32];
        #pragma unroll
        for (int k = 0; k < IN_DIM; ++k) wreg[k] = W1s[lane * IN_DIM + k];
        wreg[30] = 0.0f; wreg[31] = 0.0f;
        float t[IN_DIM];
        for (int i = 0; i < IN_DIM; ++i) {        // t = Xs * w1_lane
            const float4* x4 = reinterpret_cast<const float4*>(&scr[i * 32]);
            float acc = 0.0f;
            #pragma unroll
            for (int q = 0; q < 8; ++q) {
                float4 x = x4[q];
                acc = fmaf(x.x, wreg[4 * q + 0], acc);
                acc = fmaf(x.y, wreg[4 * q + 1], acc);
                acc = fmaf(x.z, wreg[4 * q + 2], acc);
                acc = fmaf(x.w, wreg[4 * q + 3], acc);
            }
            t[i] = acc;
        }
        #pragma unroll
        for (int r = 0; r < D1; ++r) {            // a = W1 * t (column `lane`)
            float acc = 0.0f;
            #pragma unroll
            for (int i = 0; i < IN_DIM; ++i)
                acc = fmaf(W1s[r * IN_DIM + i], t[i], acc);
            a[r] = acc;
            if (r == lane) { a[r] += EPS; dg = a[r]; }
        }
        #pragma unroll
        for (int k = 0; k < D1; ++k) vt[k] = (k == lane) ? 1.0f : 0.0f;
    }
    __syncwarp();

    // ================= eigensolve 20x20 =================================
    jacobi_smem<D1>(a, vt, dg, lane, sigma(D1, lane), SW1, rb);

    // ====== fused reeig + bimap2: C = Z Z^T,  Z = W2 * (V * sqrt(g)) ====
    float g = sqrtf(fmaxf(dg, EPS));
    #pragma unroll
    for (int k = 0; k < D1; ++k) {
        float rk = __shfl_sync(FULL, g, k);
        vt[k] *= rk;
    }
    if (lane < D1) {
        #pragma unroll
        for (int k = 0; k < D1; ++k) scr[lane * 24 + k] = vt[k]; // Vs (pitch 24)
    }
    __syncwarp();
    float z[D1];
    #pragma unroll
    for (int k = 0; k < D1; ++k) z[k] = 0.0f;
    if (lane < D2) {
        float w2r[D1];
        #pragma unroll
        for (int r = 0; r < D1; ++r) w2r[r] = W2s[lane * D1 + r];
        for (int r = 0; r < D1; ++r) {
            const float4* v4 = reinterpret_cast<const float4*>(&scr[r * 24]);
            float w = w2r[r];
            #pragma unroll
            for (int q = 0; q < 5; ++q) {
                float4 x = v4[q];
                z[4 * q + 0] = fmaf(w, x.x, z[4 * q + 0]);
                z[4 * q + 1] = fmaf(w, x.y, z[4 * q + 1]);
                z[4 * q + 2] = fmaf(w, x.z, z[4 * q + 2]);
                z[4 * q + 3] = fmaf(w, x.w, z[4 * q + 3]);
            }
        }
    }
    __syncwarp();
    if (lane < D2) {
        #pragma unroll
        for (int k = 0; k < D1; ++k) scr[480 + lane * 24 + k] = z[k]; // Zs
    }
    __syncwarp();

    float a2[16], vt2[16], dg2 = 1.0f;
    #pragma unroll
    for (int i = 0; i < 16; ++i) { a2[i] = 0.0f; vt2[i] = 0.0f; }
    if (lane < 16) {
        #pragma unroll
        for (int b = 0; b < D2; ++b) {            // A2[b][lane] = Zrow_b . z
            const float4* zb = reinterpret_cast<const float4*>(&scr[480 + b * 24]);
            float acc = 0.0f;
            #pragma unroll
            for (int q = 0; q < 5; ++q) {
                float4 x = zb[q];
                acc = fmaf(x.x, z[4 * q + 0], acc);
                acc = fmaf(x.y, z[4 * q + 1], acc);
                acc = fmaf(x.z, z[4 * q + 2], acc);
                acc = fmaf(x.w, z[4 * q + 3], acc);
            }
            a2[b] = acc;
        }
        a2[15] = 0.0f;                            // padded dim decoupled
        #pragma unroll
        for (int b = 0; b < 16; ++b)
            if (b == lane) { a2[b] += EPS; dg2 = a2[b]; }
        #pragma unroll
        for (int k = 0; k < 16; ++k) vt2[k] = (k == lane) ? 1.0f : 0.0f;
    }
    __syncwarp();

    // ================= eigensolve 16x16 (15 + 1 padded) =================
    jacobi_smem<16>(a2, vt2, dg2, lane, sigma(16, lane), SW2, rb);

    // ============== logeig recompose, upper-triangle output =============
    float lw = logf(fmaxf(dg2, EPS));
    #pragma unroll
    for (int k = 0; k < 16; ++k) {
        float lwk = __shfl_sync(FULL, lw, k);
        float raw = vt2[k];
        if (lane < D2) {
            scr[lane * 16 + k]       = raw;        // raw rows of V2
            scr[256 + lane * 16 + k] = raw * lwk;  // scaled rows
        }
    }
    __syncwarp();
    for (int tt = lane; tt < 120; tt += 32) {
        int i = 0, rem = tt;
        while (rem >= D2 - i) { rem -= D2 - i; ++i; }
        int j = i + rem;
        const float4* ri = reinterpret_cast<const float4*>(&scr[256 + i * 16]);
        const float4* rj = reinterpret_cast<const float4*>(&scr[j * 16]);
        float acc = 0.0f;
        #pragma unroll
        for (int q = 0; q < 4; ++q) {
            float4 x = ri[q], y = rj[q];
            acc = fmaf(x.x, y.x, fmaf(x.y, y.y, fmaf(x.z, y.z, fmaf(x.w, y.w, acc))));
        }
        out[(size_t)m * 120 + tt] = acc;
    }
}

extern "C" void kernel_launch(void* const* d_in, const int* in_sizes, int n_in,
                              void* d_out, int out_size) {
    const float* X  = (const float*)d_in[0];
    const float* W1 = (const float*)d_in[1];
    const float* W2 = (const float*)d_in[2];
    float* out = (float*)d_out;
    int nb = in_sizes[0] / (IN_DIM * IN_DIM);
    int blocks = (nb + WPB - 1) / WPB;
    spdnet_kernel<<<blocks, WPB * 32>>>(X, W1, W2, out, nb);
}

// round 11
// speedup vs baseline: 1.9811x; 1.0954x over previous
#include <cuda_runtime.h>

#define EPS 1e-4f
constexpr int IN_DIM = 30;
constexpr int D1 = 20;
constexpr int D2 = 15;
constexpr int WPB = 4;          // warps per block; each warp: 2 matrices
constexpr int SW1 = 5, SW2 = 5; // Jacobi sweeps per stage
constexpr int SCRN = 1536;      // floats of scratch per warp
constexpr unsigned FULL = 0xffffffffu;

// Tournament migration: NEW[l] = OLD[sigma(l)]. Position 0 fixed.
__host__ __device__ constexpr int sigma(int N, int l) {
    if (l >= N) return l;
    if (l == 0) return 0;
    if (l == N - 1) return N - 2;
    if (l & 1) return l + 2;   // odd slots move down the ring
    if (l == 2) return 1;
    return l - 2;              // even slots >= 4
}

// Parallel Jacobi over width-W lane groups with a shared round-buffer for
// rotation coefficients. rb = per-group base; layout (floats):
// cs[2][N/2 float2] at 0, diag[2][N/2] at 2N. Needs 3N floats, 16B aligned.
template <int N, int W>
__device__ __forceinline__ void jacobi_smem(float* a, float* vt, float& dg,
                                            int llane, int sig, int sweeps,
                                            float* rb) {
    const int role = llane & 1;
    const int myk = llane >> 1;
    const int kk = (myk < N / 2) ? myk : 0;   // clamp (N/2 may be non-pow2)
    int buf = 0;
    #pragma unroll 1
    for (int sw = 0; sw < sweeps; ++sw) {
        #pragma unroll 1
        for (int r = 0; r < N - 1; ++r) {
            float d_oth = __shfl_xor_sync(FULL, dg, 1);
            // --- even pair-lane computes rotation, publishes via shared ---
            if (!role && llane < N) {
                float off = 0.0f;
                #pragma unroll
                for (int k = 0; k < N / 2; ++k)
                    if (myk == k) off = a[2 * k + 1];   // off-diag A[q][p]
                float c = 1.0f, s = 0.0f, t = 0.0f;
                if (fabsf(off) > 1e-30f) {
                    float tau = (d_oth - dg) / (2.0f * off);
                    t = copysignf(1.0f, tau) /
                        (fabsf(tau) + sqrtf(fmaf(tau, tau, 1.0f)));
                    c = rsqrtf(fmaf(t, t, 1.0f));
                    s = t * c;
                }
                reinterpret_cast<float2*>(rb + buf * N)[myk] = make_float2(c, s);
                rb[2 * N + buf * (N / 2) + myk] = fmaf(t, off, d_oth); // odd diag'
                dg = fmaf(-t, off, dg);                                // even diag'
            }
            __syncwarp();
            // --- own-pair coefficients (LDS.64; broadcast within pair) ---
            float2 mycs = reinterpret_cast<const float2*>(rb + buf * N)[kk];
            float c = mycs.x, s = mycs.y;
            if (role) dg = rb[2 * N + buf * (N / 2) + kk];
            // --- column phase: A <- A*J (partner exchange via shfl_xor) ---
            float sg = role ? s : -s;
            #pragma unroll
            for (int i = 0; i < N; ++i) {
                float o = __shfl_xor_sync(FULL, a[i], 1);
                a[i] = fmaf(c, a[i], sg * o);
            }
            // --- row phase: A <- J^T*(A*J); V <- V*J; cs via LDS.128 bcast ---
            const float4* csv = reinterpret_cast<const float4*>(rb + buf * N);
            #pragma unroll
            for (int k4 = 0; k4 < N / 4; ++k4) {
                float4 q = csv[k4];
                {
                    float ck = q.x, sk = q.y;
                    float ae = a[4 * k4], ao = a[4 * k4 + 1];
                    a[4 * k4]     = fmaf(ck, ae, -sk * ao);
                    a[4 * k4 + 1] = fmaf(sk, ae,  ck * ao);
                    float ve = vt[4 * k4], vo = vt[4 * k4 + 1];
                    vt[4 * k4]     = fmaf(ck, ve, -sk * vo);
                    vt[4 * k4 + 1] = fmaf(sk, ve,  ck * vo);
                }
                {
                    float ck = q.z, sk = q.w;
                    float ae = a[4 * k4 + 2], ao = a[4 * k4 + 3];
                    a[4 * k4 + 2] = fmaf(ck, ae, -sk * ao);
                    a[4 * k4 + 3] = fmaf(sk, ae,  ck * ao);
                    float ve = vt[4 * k4 + 2], vo = vt[4 * k4 + 3];
                    vt[4 * k4 + 2] = fmaf(ck, ve, -sk * vo);
                    vt[4 * k4 + 3] = fmaf(sk, ve,  ck * vo);
                }
            }
            // --- tournament migration: rows (reg perm) + cols (lane shfl) ---
            float tmp[N];
            #pragma unroll
            for (int i = 0; i < N; ++i) tmp[i] = a[sigma(N, i)];
            #pragma unroll
            for (int i = 0; i < N; ++i) a[i] = __shfl_sync(FULL, tmp[i], sig, W);
            #pragma unroll
            for (int i = 0; i < N; ++i) tmp[i] = vt[sigma(N, i)];
            #pragma unroll
            for (int i = 0; i < N; ++i) vt[i] = tmp[i];
            dg = __shfl_sync(FULL, dg, sig, W);
            buf ^= 1;
        }
    }
}

__global__ __launch_bounds__(WPB * 32, 7)
void spdnet_kernel(const float* __restrict__ Xg,
                   const float* __restrict__ W1g,
                   const float* __restrict__ W2g,
                   float* __restrict__ out, int nb) {
    __shared__ float W1s[D1 * IN_DIM];           // 20x30
    __shared__ float W2s[D2 * D1];               // 15x20
    __shared__ __align__(16) float scr_all[WPB][SCRN];

    int tid = threadIdx.x, warp = tid >> 5, lane = tid & 31;
    for (int i = tid; i < D1 * IN_DIM; i += WPB * 32) W1s[i] = W1g[i];
    for (int i = tid; i < D2 * D1;    i += WPB * 32) W2s[i] = W2g[i];
    __syncthreads();

    int npairs = (nb + 1) >> 1;
    int wm = blockIdx.x * WPB + warp;
    if (wm >= npairs) return;      // warp-uniform; only warp-level sync below
    float* scr = scr_all[warp];

    // ============ stage 1 twice; park A2 columns (+diag) at scr[960+] =====
    #pragma unroll 1
    for (int h = 0; h < 2; ++h) {
        int m = 2 * wm + h; if (m >= nb) m = nb - 1;

        // ---- load X (pitch 32), pad, symmetrize ----
        {
            const float* xg = Xg + (size_t)m * 900;
            for (int e = lane; e < 900; e += 32) {
                int i = e / 30, k = e - i * 30;
                scr[i * 32 + k] = xg[e];
            }
            for (int e = lane; e < 60; e += 32)
                scr[(e >> 1) * 32 + 30 + (e & 1)] = 0.0f;
        }
        __syncwarp();
        for (int e = lane; e < 900; e += 32) {
            int i = e / 30, k = e - i * 30;
            if (i < k) {
                float v = 0.5f * (scr[i * 32 + k] + scr[k * 32 + i]);
                scr[i * 32 + k] = v; scr[k * 32 + i] = v;
            }
        }
        __syncwarp();

        // ---- bimap1: A = W1 * Xs * W1^T + EPS*I (column per lane) ----
        float a[D1], vt[D1], dg = 1.0f;
        #pragma unroll
        for (int i = 0; i < D1; ++i) { a[i] = 0.0f; vt[i] = 0.0f; }
        if (lane < D1) {
            float wreg[32];
            #pragma unroll
            for (int k = 0; k < IN_DIM; ++k) wreg[k] = W1s[lane * IN_DIM + k];
            wreg[30] = 0.0f; wreg[31] = 0.0f;
            float t[IN_DIM];
            for (int i = 0; i < IN_DIM; ++i) {
                const float4* x4 = reinterpret_cast<const float4*>(&scr[i * 32]);
                float acc = 0.0f;
                #pragma unroll
                for (int q = 0; q < 8; ++q) {
                    float4 x = x4[q];
                    acc = fmaf(x.x, wreg[4 * q + 0], acc);
                    acc = fmaf(x.y, wreg[4 * q + 1], acc);
                    acc = fmaf(x.z, wreg[4 * q + 2], acc);
                    acc = fmaf(x.w, wreg[4 * q + 3], acc);
                }
                t[i] = acc;
            }
            #pragma unroll
            for (int r = 0; r < D1; ++r) {
                float acc = 0.0f;
                #pragma unroll
                for (int i = 0; i < IN_DIM; ++i)
                    acc = fmaf(W1s[r * IN_DIM + i], t[i], acc);
                a[r] = acc;
                if (r == lane) { a[r] += EPS; dg = a[r]; }
            }
            #pragma unroll
            for (int k = 0; k < D1; ++k) vt[k] = (k == lane) ? 1.0f : 0.0f;
        }
        __syncwarp();

        // ---- eigensolve 20x20 (rb at scr+896; X area dead now) ----
        jacobi_smem<D1, 32>(a, vt, dg, lane, sigma(D1, lane), SW1, scr + 896);

        // ---- fused reeig + bimap2: A2 = Z Z^T + EPS*I, Z = W2*(V*sqrt) ----
        float g = sqrtf(fmaxf(dg, EPS));
        #pragma unroll
        for (int k = 0; k < D1; ++k) {
            float rk = __shfl_sync(FULL, g, k);
            vt[k] *= rk;
        }
        if (lane < D1) {
            #pragma unroll
            for (int k = 0; k < D1; ++k) scr[lane * 24 + k] = vt[k]; // Vs p24
        }
        __syncwarp();
        float z[D1];
        #pragma unroll
        for (int k = 0; k < D1; ++k) z[k] = 0.0f;
        if (lane < D2) {
            float w2r[D1];
            #pragma unroll
            for (int r = 0; r < D1; ++r) w2r[r] = W2s[lane * D1 + r];
            for (int r = 0; r < D1; ++r) {
                const float4* v4 = reinterpret_cast<const float4*>(&scr[r * 24]);
                float w = w2r[r];
                #pragma unroll
                for (int q = 0; q < 5; ++q) {
                    float4 x = v4[q];
                    z[4 * q + 0] = fmaf(w, x.x, z[4 * q + 0]);
                    z[4 * q + 1] = fmaf(w, x.y, z[4 * q + 1]);
                    z[4 * q + 2] = fmaf(w, x.z, z[4 * q + 2]);
                    z[4 * q + 3] = fmaf(w, x.w, z[4 * q + 3]);
                }
            }
        }
        __syncwarp();
        if (lane < D2) {
            #pragma unroll
            for (int k = 0; k < D1; ++k) scr[480 + lane * 24 + k] = z[k]; // Zs
        }
        __syncwarp();

        if (lane < 16) {
            float a2[16];
            #pragma unroll
            for (int b = 0; b < D2; ++b) {        // A2[b][lane] = Zrow_b . z
                const float4* zb = reinterpret_cast<const float4*>(&scr[480 + b * 24]);
                float acc = 0.0f;
                #pragma unroll
                for (int q = 0; q < 5; ++q) {
                    float4 x = zb[q];
                    acc = fmaf(x.x, z[4 * q + 0], acc);
                    acc = fmaf(x.y, z[4 * q + 1], acc);
                    acc = fmaf(x.z, z[4 * q + 2], acc);
                    acc = fmaf(x.w, z[4 * q + 3], acc);
                }
                a2[b] = acc;
            }
            a2[15] = 0.0f;                        // padded dim decoupled
            a2[lane] += EPS;
            // park A2 column + diag
            float4* dst = reinterpret_cast<float4*>(&scr[960 + h * 272 + lane * 16]);
            const float4* src = reinterpret_cast<const float4*>(a2);
            #pragma unroll
            for (int q = 0; q < 4; ++q) dst[q] = src[q];
            scr[960 + h * 272 + 256 + lane] = a2[lane];
        }
        __syncwarp();
    }

    // ====== dual 16x16 eigensolve: lanes 0-15 mat 0, lanes 16-31 mat 1 =====
    int g2 = lane >> 4, llane = lane & 15;
    float A2[16], vt2[16];
    {
        const float4* src = reinterpret_cast<const float4*>(&scr[960 + g2 * 272 + llane * 16]);
        float4* dst = reinterpret_cast<float4*>(A2);
        #pragma unroll
        for (int q = 0; q < 4; ++q) dst[q] = src[q];
    }
    float dg2 = scr[960 + g2 * 272 + 256 + llane];
    #pragma unroll
    for (int k = 0; k < 16; ++k) vt2[k] = (k == llane) ? 1.0f : 0.0f;
    __syncwarp();

    // rb for the two groups at scr[0..96) (Vs/Zs dead)
    jacobi_smem<16, 16>(A2, vt2, dg2, llane, sigma(16, llane), SW2,
                        scr + g2 * 48);

    // ============== logeig recompose (per group), triangle output =========
    float lw = logf(fmaxf(dg2, EPS));
    __syncwarp();   // rb reads done before recompose overwrites scr[0..96)
    #pragma unroll
    for (int k = 0; k < 16; ++k) {
        float lwk = __shfl_sync(FULL, lw, k, 16);
        float raw = vt2[k];
        if (llane < D2) {
            scr[g2 * 512 + llane * 16 + k]       = raw;        // raw rows
            scr[g2 * 512 + 256 + llane * 16 + k] = raw * lwk;  // scaled rows
        }
    }
    __syncwarp();

    int m = 2 * wm + g2;
    if (m < nb) {
        const float* base = &scr[g2 * 512];
        for (int tt = llane; tt < 120; tt += 16) {
            int i = 0, rem = tt;
            while (rem >= D2 - i) { rem -= D2 - i; ++i; }
            int j = i + rem;
            const float4* ri = reinterpret_cast<const float4*>(&base[256 + i * 16]);
            const float4* rj = reinterpret_cast<const float4*>(&base[j * 16]);
            float acc = 0.0f;
            #pragma unroll
            for (int q = 0; q < 4; ++q) {
                float4 x = ri[q], y = rj[q];
                acc = fmaf(x.x, y.x, fmaf(x.y, y.y, fmaf(x.z, y.z, fmaf(x.w, y.w, acc))));
            }
            out[(size_t)m * 120 + tt] = acc;
        }
    }
}

extern "C" void kernel_launch(void* const* d_in, const int* in_sizes, int n_in,
                              void* d_out, int out_size) {
    const float* X  = (const float*)d_in[0];
    const float* W1 = (const float*)d_in[1];
    const float* W2 = (const float*)d_in[2];
    float* out = (float*)d_out;
    int nb = in_sizes[0] / (IN_DIM * IN_DIM);
    int npairs = (nb + 1) / 2;
    int blocks = (npairs + WPB - 1) / WPB;
    spdnet_kernel<<<blocks, WPB * 32>>>(X, W1, W2, out, nb);
}